// round 11
// baseline (speedup 1.0000x reference)
#include <cuda_runtime.h>
#include <cuda_bf16.h>
#include <cstdint>

typedef unsigned int u32;
typedef unsigned long long u64;

#define A_NUM   3
#define SHW     (32 * 128 * 128)            // 2^19
#define N_SC    (A_NUM * SHW)               // 1572864
#define N_SC4   (N_SC / 4)                  // 393216
#define PRE_TOPN  2000
#define POST_TOPN 300
#define NMS_T     0.7f
#define MASK_COLS 32
#define CAND_CAP  4096                      // ~2400 expected with 20-bit threshold

#define NBLK 148
#define NTHR 1024
#define GSTRIDE (NBLK * NTHR)               // 151552
#define THIRD_BLKS 88                       // N_SC4 = 2*GSTRIDE + 88*1024

__device__ u32  g_hist1[4096];
__device__ __align__(16) u32 g_fine[1 << 20];   // 20-bit-key histogram (4MB)
__device__ int  g_ccount;
__device__ u64  g_cand[CAND_CAP];
__device__ int  g_order[PRE_TOPN];
__device__ float g_score[PRE_TOPN];
__device__ float4 g_bx4[PRE_TOPN * 2];      // per box: {x1,y1,z1,x2},{y2,z2,vol,0}
__device__ u64  g_invalid[32];
__device__ u64  g_mask[PRE_TOPN * MASK_COLS];
__device__ volatile u32 g_arrive[NBLK];
__device__ volatile u32 g_release;

__device__ __forceinline__ u32 fkey(float f) {
    u32 b = __float_as_uint(f);
    return b ^ ((b & 0x80000000u) ? 0xFFFFFFFFu : 0x80000000u);
}

// Distributed flag barrier: per-block arrival flags (distinct addresses).
__device__ __forceinline__ void gbar(u32 e, bool wait_release) {
    __syncthreads();
    if (blockIdx.x == 0) {
        if (threadIdx.x > 0 && threadIdx.x < NBLK)
            while (g_arrive[threadIdx.x] < e) __nanosleep(32);
        __threadfence();
        __syncthreads();
        if (threadIdx.x == 0) g_release = e;
    } else {
        if (threadIdx.x == 0) {
            __threadfence();
            g_arrive[blockIdx.x] = e;
            if (wait_release) {
                while (g_release < e) __nanosleep(32);
                __threadfence();
            }
        }
        __syncthreads();
    }
}

// All-blocks histogram select (read-only): bucket containing the `target`-th
// element counting from the top of a 4096-bucket histogram.
__device__ __forceinline__ void find_bucket(const u32* __restrict__ hist, u32 target,
                                            u32* ws, u32* sres,
                                            u32& out_b, u32& out_above) {
    const int tid = threadIdx.x, lane = tid & 31, wid = tid >> 5;
    const int base = 4095 - tid * 4;
    u32 v0 = hist[base], v1 = hist[base - 1], v2 = hist[base - 2], v3 = hist[base - 3];
    u32 s = v0 + v1 + v2 + v3;
    u32 x = s;
#pragma unroll
    for (int off = 1; off < 32; off <<= 1) {
        u32 y = __shfl_up_sync(0xFFFFFFFFu, x, off);
        if (lane >= off) x += y;
    }
    if (lane == 31) ws[wid] = x;
    __syncthreads();
    if (wid == 0) {
        u32 wv = ws[lane];
        u32 wx = wv;
#pragma unroll
        for (int off = 1; off < 32; off <<= 1) {
            u32 y = __shfl_up_sync(0xFFFFFFFFu, wx, off);
            if (lane >= off) wx += y;
        }
        ws[lane] = wx - wv;
    }
    __syncthreads();
    u32 incl = x + ws[wid];
    u32 excl = incl - s;
    if (excl < target && incl >= target) {
        u32 cum = excl;
        u32 vv[4] = {v0, v1, v2, v3};
#pragma unroll
        for (int k = 0; k < 4; k++) {
            if (cum + vv[k] >= target) { sres[0] = (u32)(base - k); sres[1] = cum; break; }
            cum += vv[k];
        }
    }
    __syncthreads();
    out_b = sres[0];
    out_above = sres[1];
    __syncthreads();
}

// Warp-aggregated append of predicated items to a global list.
__device__ __forceinline__ void wappend(bool pred, u64 item, int* counter,
                                        u64* list, int cap) {
    const int lane = threadIdx.x & 31;
    u32 bal = __ballot_sync(0xFFFFFFFFu, pred);
    if (bal) {
        int leader = __ffs(bal) - 1;
        int posb = 0;
        if (lane == leader) posb = atomicAdd(counter, __popc(bal));
        posb = __shfl_sync(0xFFFFFFFFu, posb, leader);
        if (pred) {
            int pos = posb + __popc(bal & ((1u << lane) - 1u));
            if (pos < cap) list[pos] = item;
        }
    }
}

__device__ __forceinline__ void decode_box(u64 myk, int rank,
                                           const float* __restrict__ deltas,
                                           const float* __restrict__ imi,
                                           const float* __restrict__ anchors) {
    u32 k = (u32)(myk >> 32);
    u32 r = 0xFFFFFFFFu - (u32)(myk & 0xFFFFFFFFu);
    g_order[rank] = (int)r;
    u32 bits = (k & 0x80000000u) ? (k ^ 0x80000000u) : ~k;
    g_score[rank] = __uint_as_float(bits);
    int a   = (int)(r % A_NUM);
    int shw = (int)(r / A_NUM);
    int w = shw & 127, h = (shw >> 7) & 127, sd = shw >> 14;
    float sx = (float)w * 4.0f, sy = (float)h * 4.0f, sz = (float)sd * 4.0f;
    float ax1 = sx + anchors[a * 6 + 0];
    float ay1 = sy + anchors[a * 6 + 1];
    float az1 = sz + anchors[a * 6 + 2];
    float ax2 = sx + anchors[a * 6 + 3];
    float ay2 = sy + anchors[a * 6 + 4];
    float az2 = sz + anchors[a * 6 + 5];
    float wA = ax2 - ax1 + 1.0f, hA = ay2 - ay1 + 1.0f, dA = az2 - az1 + 1.0f;
    float cx = ax1 + 0.5f * wA, cy = ay1 + 0.5f * hA, cz = az1 + 0.5f * dA;
    const float* dp = deltas + (size_t)(a * 6) * SHW + shw;
    float d0 = dp[0 * SHW], d1 = dp[1 * SHW], d2 = dp[2 * SHW];
    float d3 = dp[3 * SHW], d4 = dp[4 * SHW], d5 = dp[5 * SHW];
    float pcx = d0 * wA + cx, pcy = d1 * hA + cy, pcz = d2 * dA + cz;
    float pw = expf(d3) * wA, ph = expf(d4) * hA, pd = expf(d5) * dA;
    float slices = imi[0], height = imi[1], width = imi[2], scale = imi[3];
    float x1 = fminf(fmaxf(pcx - 0.5f * pw, 0.0f), width  - 1.0f);
    float y1 = fminf(fmaxf(pcy - 0.5f * ph, 0.0f), height - 1.0f);
    float z1 = fminf(fmaxf(pcz - 0.5f * pd, 0.0f), slices - 1.0f);
    float x2 = fminf(fmaxf(pcx + 0.5f * pw - 1.0f, 0.0f), width  - 1.0f);
    float y2 = fminf(fmaxf(pcy + 0.5f * ph - 1.0f, 0.0f), height - 1.0f);
    float z2 = fminf(fmaxf(pcz + 0.5f * pd - 1.0f, 0.0f), slices - 1.0f);
    float vol = (x2 - x1 + 1.0f) * (y2 - y1 + 1.0f) * (z2 - z1 + 1.0f);
    g_bx4[rank * 2 + 0] = make_float4(x1, y1, z1, x2);
    g_bx4[rank * 2 + 1] = make_float4(y2, z2, vol, 0.0f);
    float ss = x2 - x1 + 1.0f;
    float xc = x1 + ss * 0.5f, yc = y1 + ss * 0.5f, zc = z1 + ss * 0.5f;
    bool valid = (ss >= 8.0f * scale) && (xc < width) && (yc < height) && (zc < slices);
    if (!valid) atomicOr(&g_invalid[rank >> 6], 1ULL << (rank & 63));
}

#define SM_BYTES 34048
__global__ void __launch_bounds__(NTHR, 1)
k_all(const float4* __restrict__ sc4, const float* __restrict__ deltas,
      const float* __restrict__ imi, const float* __restrict__ anchors,
      float* __restrict__ out) {
    __shared__ __align__(16) char smraw[SM_BYTES];
    __shared__ u32 ws[32];
    __shared__ u32 sres[2];
    __shared__ u32 fws[8];
    const int tid = threadIdx.x;
    const int bid = blockIdx.x;
    const int lane = tid & 31;
    const int i0 = bid * NTHR + tid;
    const bool third = (bid < THIRD_BLKS);
    const int nf = third ? 12 : 8;

    // Load this thread's scores ONCE; keep in registers across phases 1-2.
    float f[12];
    {
        float4 v0 = sc4[i0];
        float4 v1 = sc4[i0 + GSTRIDE];
        f[0] = v0.x; f[1] = v0.y; f[2] = v0.z; f[3] = v0.w;
        f[4] = v1.x; f[5] = v1.y; f[6] = v1.z; f[7] = v1.w;
        if (third) {
            float4 v2 = sc4[i0 + 2 * GSTRIDE];
            f[8] = v2.x; f[9] = v2.y; f[10] = v2.z; f[11] = v2.w;
        } else {
            f[8] = f[9] = f[10] = f[11] = 0.0f;
        }
    }

    // ------- P1: coarse (smem, warp-agg) + fine (global RED) histograms -------
    {
        u32* sh = (u32*)smraw;
        for (int i = tid; i < 4096; i += NTHR) sh[i] = 0u;
        __syncthreads();
#pragma unroll
        for (int j = 0; j < 12; j++) {
            if (j >= nf) break;            // block-uniform
            u32 k = fkey(f[j]);
            atomicAdd(&g_fine[k >> 12], 1u);          // fire-and-forget RED
            u32 b = k >> 20;
            u32 m = __match_any_sync(0xFFFFFFFFu, b);
            if ((__ffs(m) - 1) == lane) atomicAdd(&sh[b], __popc(m));
        }
        __syncthreads();
        for (int i = tid; i < 4096; i += NTHR)
            if (sh[i]) atomicAdd(&g_hist1[i], sh[i]);
    }
    gbar(1, true);

    // ------- P2: find1 + fine 256-bucket refine + gather from registers -------
    {
        u32 b1, above1;
        find_bucket(g_hist1, PRE_TOPN, ws, sres, b1, above1);
        if (bid == 0 && tid < 32)
            g_invalid[tid] = (tid == 31) ? 0xFFFFFFFFFFFF0000ULL : 0ULL;
        // fine refine: suffix-find over the 256 fine buckets inside coarse b1
        u32 target2 = PRE_TOPN - above1;
        u32 v = (tid < 256) ? g_fine[(b1 << 8) + 255 - tid] : 0u;
        u32 x = v;
#pragma unroll
        for (int off = 1; off < 32; off <<= 1) {
            u32 y = __shfl_up_sync(0xFFFFFFFFu, x, off);
            if (lane >= off) x += y;
        }
        if (tid < 256 && lane == 31) fws[tid >> 5] = x;
        __syncthreads();
        if (tid == 0) {
            u32 acc = 0;
#pragma unroll
            for (int wq = 0; wq < 8; wq++) { u32 t2 = fws[wq]; fws[wq] = acc; acc += t2; }
        }
        __syncthreads();
        if (tid < 256) {
            u32 incl = x + fws[tid >> 5];
            u32 excl = incl - v;
            if (excl < target2 && incl >= target2) sres[0] = (u32)(255 - tid);
        }
        __syncthreads();
        u32 thr20 = (b1 << 8) | sres[0];
        __syncthreads();
#pragma unroll
        for (int j = 0; j < 12; j++) {
            if (j >= nf) break;
            u32 k = fkey(f[j]);
            bool pred = ((k >> 12) >= thr20);
            int m = (i0 + (j >> 2) * GSTRIDE) * 4 + (j & 3);
            int a = m >> 19;
            int shw = m & (SHW - 1);
            u32 r = (u32)(shw * A_NUM + a);
            u64 item = ((u64)k << 32) | (0xFFFFFFFFu - r);
            wappend(pred, item, &g_ccount, g_cand, CAND_CAP);
        }
    }
    gbar(2, true);

    // ------ P3: rank (warp per candidate, full smem staging) + decode ------
    {
        int cc = g_ccount; if (cc > CAND_CAP) cc = CAND_CAP;
        u64* st = (u64*)smraw;                       // <=4096 u64 = 32KB
        for (int j = tid; j < cc; j += NTHR) st[j] = g_cand[j];
        __syncthreads();
        int w = tid >> 5;
        int c = bid * 32 + w;                        // capacity 4736 >= cc
        if (c < cc) {
            u64 myk = st[c];
            u32 partial = 0;
            for (int j = lane; j < cc; j += 32) partial += (st[j] > myk);
#pragma unroll
            for (int off = 16; off > 0; off >>= 1)
                partial += __shfl_xor_sync(0xFFFFFFFFu, partial, off);
            if (lane == 0) {
                int rank = (int)partial;
                if (rank < PRE_TOPN) decode_box(myk, rank, deltas, imi, anchors);
            }
        }
        // replay reset: coarse hist (read finished at G2)
        for (int i = i0; i < 4096; i += GSTRIDE) g_hist1[i] = 0u;
    }
    gbar(3, true);

    // ---------- P4: IoU masks; lower-triangle tiles write zeros ----------
    {
        if (bid == 0 && tid == 0) g_ccount = 0;      // reset for next replay
        float4* cbbv = (float4*)smraw + (tid >> 6) * 128;   // [64][2] float4 per group
        int grp = tid >> 6, lt = tid & 63;
        int tile = bid * 16 + grp;
        int rb = tile >> 5, cbi = tile & 31;
        bool act  = (tile < 1024) && (cbi >= rb);
        bool zero = (tile < 1024) && (cbi < rb);
        if (act) {
            int j = cbi * 64 + lt;
            if (j < PRE_TOPN) {
                cbbv[lt * 2 + 0] = g_bx4[j * 2 + 0];
                cbbv[lt * 2 + 1] = g_bx4[j * 2 + 1];
            }
        }
        __syncthreads();
        if (zero) {
            int i = rb * 64 + lt;
            if (i < PRE_TOPN) g_mask[i * MASK_COLS + cbi] = 0ULL;
        }
        if (act) {
            int i = rb * 64 + lt;
            if (i < PRE_TOPN) {
                float4 lo = g_bx4[i * 2 + 0];
                float4 hi = g_bx4[i * 2 + 1];
                float x1 = lo.x, y1 = lo.y, z1 = lo.z, x2 = lo.w;
                float y2 = hi.x, z2 = hi.y, vi = hi.z;
                u64 word = 0ULL;
                int jn = min(64, PRE_TOPN - cbi * 64);
                for (int jj = 0; jj < jn; jj++) {
                    int jg = cbi * 64 + jj;
                    if (jg <= i) continue;
                    float4 cl = cbbv[jj * 2 + 0];
                    float4 ch = cbbv[jj * 2 + 1];
                    float iw  = fminf(x2, cl.w) - fmaxf(x1, cl.x) + 1.0f;
                    float ih  = fminf(y2, ch.x) - fmaxf(y1, cl.y) + 1.0f;
                    float idd = fminf(z2, ch.y) - fmaxf(z1, cl.z) + 1.0f;
                    iw = fmaxf(iw, 0.0f); ih = fmaxf(ih, 0.0f); idd = fmaxf(idd, 0.0f);
                    float inter = iw * ih * idd;
                    float iou = inter / (vi + ch.z - inter);
                    if (iou > NMS_T) word |= (1ULL << jj);
                }
                g_mask[i * MASK_COLS + cbi] = word;
            }
        }
    }
    gbar(4, false);   // arrive-only for non-zero blocks

    // -- non-NMS blocks: zero the fine histogram (off critical path), exit --
    if (bid != 0) {
        uint4* gz = (uint4*)g_fine;                  // 256K uint4
        const uint4 z4 = make_uint4(0u, 0u, 0u, 0u);
        for (int i = (bid - 1) * NTHR + tid; i < (1 << 18); i += (NBLK - 1) * NTHR)
            gz[i] = z4;
        return;
    }

    // ---------------- P6: speculative batch NMS + output (block 0) ----------------
    {
        u64* buf    = (u64*)smraw;                 // 2 x 2048 u64 = 32KB
        int* keep_s = (int*)(smraw + 32768);       // 300 ints
        int* s_nk   = (int*)(smraw + 32768 + 1200);
        int* s_flag = (int*)(smraw + 32768 + 1204);
        if (tid == 0) { *s_flag = 0; *s_nk = 0; }
        u64 remv = 0ULL;
        if (tid < 32) remv = g_invalid[tid];
        for (int k = tid; k < 64 * MASK_COLS; k += NTHR) buf[k] = g_mask[k];
        __syncthreads();

        int nk = 0;
        for (int c = 0; c < MASK_COLS; c++) {
            if (tid >= 32 && c + 1 < MASK_COLS) {
                int r0n = (c + 1) * 64;
                int rnn = min(64, PRE_TOPN - r0n);
                u64* dst = buf + ((c + 1) & 1) * 2048;
                for (int k = tid - 32; k < rnn * MASK_COLS; k += (NTHR - 32))
                    dst[k] = g_mask[r0n * MASK_COLS + k];
            }
            if (tid < 32) {
                const u64* sb = buf + (c & 1) * 2048;
                // preload this lane's two broadcast-column words (rows lane, lane+32)
                u64 mcA = sb[lane * 32 + c];
                u64 mcB = sb[(lane + 32) * 32 + c];
                u64 cur = __shfl_sync(0xFFFFFFFFu, remv, c);
                u64 K = ~cur;                      // speculative keep set
                // iterate: drop genuinely-suppressed boxes until consistent
                while (true) {
                    u64 contrib = 0ULL;
                    if ((K >> lane) & 1ULL)
                        contrib |= mcA & ((0xFFFFFFFFFFFFFFFFULL << lane) << 1);
                    if ((K >> (lane + 32)) & 1ULL)
                        contrib |= mcB & ((0xFFFFFFFFFFFFFFFFULL << (lane + 32)) << 1);
                    u32 ulo = __reduce_or_sync(0xFFFFFFFFu, (u32)contrib);
                    u32 uhi = __reduce_or_sync(0xFFFFFFFFu, (u32)(contrib >> 32));
                    u64 U = ((u64)uhi << 32) | ulo;
                    u64 V = K & U;
                    if (!V) break;
                    K &= ~(V & (~V + 1ULL));       // drop lowest (first) violator
                }
                int cnt = __popcll(K);
                int take = min(cnt, POST_TOPN - nk);
                u64 C = K;
                for (int d = cnt - take; d > 0; d--)       // trim to quota (rare)
                    C &= ~(0x8000000000000000ULL >> __clzll(C));
                // parallel keep_s writes in rank order
                if ((C >> lane) & 1ULL) {
                    int pos = nk + __popcll(C & ((1ULL << lane) - 1ULL));
                    keep_s[pos] = c * 64 + lane;
                }
                if ((C >> (lane + 32)) & 1ULL) {
                    int pos = nk + (int)__popcll(C & (((1ULL << (lane + 32)) - 1ULL)));
                    keep_s[pos] = c * 64 + lane + 32;
                }
                nk += take;
                // fold committed rows into remv (parallel across lanes)
                u64 CC = C;
                while (CC) {
                    int b = __ffsll((long long)CC) - 1;
                    CC &= CC - 1ULL;
                    remv |= sb[b * 32 + lane];
                }
                if (lane == 0 && (nk >= POST_TOPN || c == MASK_COLS - 1)) {
                    *s_nk = nk; *s_flag = 1;
                }
            }
            __syncthreads();
            if (*s_flag) break;
        }

        int nkf = *s_nk;
        float* rois = out;
        float* sc   = out + POST_TOPN * 7;
        float* ki   = out + POST_TOPN * 7 + POST_TOPN;
        float* sv   = out + POST_TOPN * 7 + 2 * POST_TOPN;
        for (int p = tid; p < POST_TOPN; p += NTHR) {
            if (p < nkf) {
                int i = keep_s[p];
                float4 lo = g_bx4[i * 2 + 0];
                float4 hi = g_bx4[i * 2 + 1];
                rois[p * 7 + 0] = 0.0f;
                rois[p * 7 + 1] = lo.x;
                rois[p * 7 + 2] = lo.y;
                rois[p * 7 + 3] = lo.z;
                rois[p * 7 + 4] = lo.w;
                rois[p * 7 + 5] = hi.x;
                rois[p * 7 + 6] = hi.y;
                sc[p] = g_score[i];
                ki[p] = (float)g_order[i];
                sv[p] = 1.0f;
            } else {
#pragma unroll
                for (int q = 0; q < 7; q++) rois[p * 7 + q] = 0.0f;
                sc[p] = 0.0f;
                ki[p] = -1.0f;
                sv[p] = 0.0f;
            }
        }
        // reset barrier state for next graph replay (all arrivals observed)
        __syncthreads();
        if (tid < NBLK) g_arrive[tid] = 0u;
        if (tid == 0) g_release = 0u;
    }
}

extern "C" void kernel_launch(void* const* d_in, const int* in_sizes, int n_in,
                              void* d_out, int out_size) {
    const float4* scores = (const float4*)d_in[0];
    const float*  deltas = (const float*)d_in[1];
    const float*  im_info = (const float*)d_in[2];
    const float*  anchors = (const float*)d_in[3];
    float* out = (float*)d_out;
    k_all<<<NBLK, NTHR>>>(scores, deltas, im_info, anchors, out);
    (void)in_sizes; (void)n_in; (void)out_size;
}

// round 13
// speedup vs baseline: 1.3135x; 1.3135x over previous
#include <cuda_runtime.h>
#include <cuda_bf16.h>
#include <cstdint>

typedef unsigned int u32;
typedef unsigned long long u64;

#define A_NUM   3
#define SHW     (32 * 128 * 128)            // 2^19
#define N_SC    (A_NUM * SHW)               // 1572864
#define N_SC4   (N_SC / 4)                  // 393216
#define PRE_TOPN  2000
#define POST_TOPN 300
#define NMS_T     0.7f
#define MASK_COLS 32
#define CAND_CAP  4096
#define CHUNKS_FAST 8                        // mask rows precomputed: 8*64 = 512

#define NBLK 148
#define NTHR 1024
#define GSTRIDE (NBLK * NTHR)               // 151552
#define THIRD_BLKS 88                       // N_SC4 = 2*GSTRIDE + 88*1024

__device__ u32  g_hist1[4096];
__device__ u32  g_hist2[4096];
__device__ int  g_ccount;
__device__ u64  g_cand[CAND_CAP];
__device__ int  g_order[PRE_TOPN];
__device__ float g_score[PRE_TOPN];
__device__ float4 g_bx4[PRE_TOPN * 2];      // per box: {x1,y1,z1,x2},{y2,z2,vol,0}
__device__ u64  g_invalid[32];
__device__ u64  g_mask[PRE_TOPN * MASK_COLS];
__device__ volatile u32 g_arrive[NBLK];
__device__ volatile u32 g_release;

__device__ __forceinline__ u32 fkey(float f) {
    u32 b = __float_as_uint(f);
    return b ^ ((b & 0x80000000u) ? 0xFFFFFFFFu : 0x80000000u);
}

// Distributed flag barrier: per-block arrival flags (distinct addresses).
__device__ __forceinline__ void gbar(u32 e, bool wait_release) {
    __syncthreads();
    if (blockIdx.x == 0) {
        if (threadIdx.x > 0 && threadIdx.x < NBLK)
            while (g_arrive[threadIdx.x] < e) __nanosleep(32);
        __threadfence();
        __syncthreads();
        if (threadIdx.x == 0) g_release = e;
    } else {
        if (threadIdx.x == 0) {
            __threadfence();
            g_arrive[blockIdx.x] = e;
            if (wait_release) {
                while (g_release < e) __nanosleep(32);
                __threadfence();
            }
        }
        __syncthreads();
    }
}

// All-blocks histogram select (read-only): bucket containing the `target`-th
// element counting from the top of a 4096-bucket histogram.
__device__ __forceinline__ void find_bucket(const u32* __restrict__ hist, u32 target,
                                            u32* ws, u32* sres,
                                            u32& out_b, u32& out_above) {
    const int tid = threadIdx.x, lane = tid & 31, wid = tid >> 5;
    const int base = 4095 - tid * 4;
    u32 v0 = hist[base], v1 = hist[base - 1], v2 = hist[base - 2], v3 = hist[base - 3];
    u32 s = v0 + v1 + v2 + v3;
    u32 x = s;
#pragma unroll
    for (int off = 1; off < 32; off <<= 1) {
        u32 y = __shfl_up_sync(0xFFFFFFFFu, x, off);
        if (lane >= off) x += y;
    }
    if (lane == 31) ws[wid] = x;
    __syncthreads();
    if (wid == 0) {
        u32 wv = ws[lane];
        u32 wx = wv;
#pragma unroll
        for (int off = 1; off < 32; off <<= 1) {
            u32 y = __shfl_up_sync(0xFFFFFFFFu, wx, off);
            if (lane >= off) wx += y;
        }
        ws[lane] = wx - wv;
    }
    __syncthreads();
    u32 incl = x + ws[wid];
    u32 excl = incl - s;
    if (excl < target && incl >= target) {
        u32 cum = excl;
        u32 vv[4] = {v0, v1, v2, v3};
#pragma unroll
        for (int k = 0; k < 4; k++) {
            if (cum + vv[k] >= target) { sres[0] = (u32)(base - k); sres[1] = cum; break; }
            cum += vv[k];
        }
    }
    __syncthreads();
    out_b = sres[0];
    out_above = sres[1];
    __syncthreads();
}

// Warp-aggregated append of predicated items to a global list.
__device__ __forceinline__ void wappend(bool pred, u64 item, int* counter,
                                        u64* list, int cap) {
    const int lane = threadIdx.x & 31;
    u32 bal = __ballot_sync(0xFFFFFFFFu, pred);
    if (bal) {
        int leader = __ffs(bal) - 1;
        int posb = 0;
        if (lane == leader) posb = atomicAdd(counter, __popc(bal));
        posb = __shfl_sync(0xFFFFFFFFu, posb, leader);
        if (pred) {
            int pos = posb + __popc(bal & ((1u << lane) - 1u));
            if (pos < cap) list[pos] = item;
        }
    }
}

__device__ __forceinline__ void decode_box(u64 myk, int rank,
                                           const float* __restrict__ deltas,
                                           const float* __restrict__ imi,
                                           const float* __restrict__ anchors) {
    u32 k = (u32)(myk >> 32);
    u32 r = 0xFFFFFFFFu - (u32)(myk & 0xFFFFFFFFu);
    g_order[rank] = (int)r;
    u32 bits = (k & 0x80000000u) ? (k ^ 0x80000000u) : ~k;
    g_score[rank] = __uint_as_float(bits);
    int a   = (int)(r % A_NUM);
    int shw = (int)(r / A_NUM);
    int w = shw & 127, h = (shw >> 7) & 127, sd = shw >> 14;
    float sx = (float)w * 4.0f, sy = (float)h * 4.0f, sz = (float)sd * 4.0f;
    float ax1 = sx + anchors[a * 6 + 0];
    float ay1 = sy + anchors[a * 6 + 1];
    float az1 = sz + anchors[a * 6 + 2];
    float ax2 = sx + anchors[a * 6 + 3];
    float ay2 = sy + anchors[a * 6 + 4];
    float az2 = sz + anchors[a * 6 + 5];
    float wA = ax2 - ax1 + 1.0f, hA = ay2 - ay1 + 1.0f, dA = az2 - az1 + 1.0f;
    float cx = ax1 + 0.5f * wA, cy = ay1 + 0.5f * hA, cz = az1 + 0.5f * dA;
    const float* dp = deltas + (size_t)(a * 6) * SHW + shw;
    float d0 = dp[0 * SHW], d1 = dp[1 * SHW], d2 = dp[2 * SHW];
    float d3 = dp[3 * SHW], d4 = dp[4 * SHW], d5 = dp[5 * SHW];
    float pcx = d0 * wA + cx, pcy = d1 * hA + cy, pcz = d2 * dA + cz;
    float pw = expf(d3) * wA, ph = expf(d4) * hA, pd = expf(d5) * dA;
    float slices = imi[0], height = imi[1], width = imi[2], scale = imi[3];
    float x1 = fminf(fmaxf(pcx - 0.5f * pw, 0.0f), width  - 1.0f);
    float y1 = fminf(fmaxf(pcy - 0.5f * ph, 0.0f), height - 1.0f);
    float z1 = fminf(fmaxf(pcz - 0.5f * pd, 0.0f), slices - 1.0f);
    float x2 = fminf(fmaxf(pcx + 0.5f * pw - 1.0f, 0.0f), width  - 1.0f);
    float y2 = fminf(fmaxf(pcy + 0.5f * ph - 1.0f, 0.0f), height - 1.0f);
    float z2 = fminf(fmaxf(pcz + 0.5f * pd - 1.0f, 0.0f), slices - 1.0f);
    float vol = (x2 - x1 + 1.0f) * (y2 - y1 + 1.0f) * (z2 - z1 + 1.0f);
    g_bx4[rank * 2 + 0] = make_float4(x1, y1, z1, x2);
    g_bx4[rank * 2 + 1] = make_float4(y2, z2, vol, 0.0f);
    float ss = x2 - x1 + 1.0f;
    float xc = x1 + ss * 0.5f, yc = y1 + ss * 0.5f, zc = z1 + ss * 0.5f;
    bool valid = (ss >= 8.0f * scale) && (xc < width) && (yc < height) && (zc < slices);
    if (!valid) atomicOr(&g_invalid[rank >> 6], 1ULL << (rank & 63));
}

// IoU mask word: row i vs 64 boxes [cbi*64, cbi*64+64) given in cl/ch arrays.
__device__ __forceinline__ u64 mask_word(int i, int cbi,
                                         float x1, float y1, float z1, float x2,
                                         float y2, float z2, float vi,
                                         const float4* cl2) {
    u64 word = 0ULL;
    int jn = min(64, PRE_TOPN - cbi * 64);
    for (int jj = 0; jj < jn; jj++) {
        int jg = cbi * 64 + jj;
        if (jg <= i) continue;
        float4 cl = cl2[jj * 2 + 0];
        float4 ch = cl2[jj * 2 + 1];
        float iw  = fminf(x2, cl.w) - fmaxf(x1, cl.x) + 1.0f;
        float ih  = fminf(y2, ch.x) - fmaxf(y1, cl.y) + 1.0f;
        float idd = fminf(z2, ch.y) - fmaxf(z1, cl.z) + 1.0f;
        iw = fmaxf(iw, 0.0f); ih = fmaxf(ih, 0.0f); idd = fmaxf(idd, 0.0f);
        float inter = iw * ih * idd;
        float iou = inter / (vi + ch.z - inter);
        if (iou > NMS_T) word |= (1ULL << jj);
    }
    return word;
}

#define SM_BYTES 34048
__global__ void __launch_bounds__(NTHR, 1)
k_all(const float4* __restrict__ sc4, const float* __restrict__ deltas,
      const float* __restrict__ imi, const float* __restrict__ anchors,
      float* __restrict__ out) {
    __shared__ __align__(16) char smraw[SM_BYTES];
    __shared__ u32 ws[32];
    __shared__ u32 sres[2];
    const int tid = threadIdx.x;
    const int bid = blockIdx.x;
    const int lane = tid & 31;
    const int i0 = bid * NTHR + tid;
    const bool third = (bid < THIRD_BLKS);
    const int nf = third ? 12 : 8;

    // Load this thread's scores ONCE; keep in registers across phases 1-3.
    float f[12];
    {
        float4 v0 = sc4[i0];
        float4 v1 = sc4[i0 + GSTRIDE];
        f[0] = v0.x; f[1] = v0.y; f[2] = v0.z; f[3] = v0.w;
        f[4] = v1.x; f[5] = v1.y; f[6] = v1.z; f[7] = v1.w;
        if (third) {
            float4 v2 = sc4[i0 + 2 * GSTRIDE];
            f[8] = v2.x; f[9] = v2.y; f[10] = v2.z; f[11] = v2.w;
        } else {
            f[8] = f[9] = f[10] = f[11] = 0.0f;
        }
    }

    // ---------------- P1: coarse 12-bit histogram of all scores ----------------
    {
        u32* sh = (u32*)smraw;
        for (int i = tid; i < 4096; i += NTHR) sh[i] = 0u;
        __syncthreads();
#pragma unroll
        for (int j = 0; j < 12; j++) {
            if (j >= nf) break;            // block-uniform
            u32 b = fkey(f[j]) >> 20;
            u32 m = __match_any_sync(0xFFFFFFFFu, b);
            if ((__ffs(m) - 1) == lane) atomicAdd(&sh[b], __popc(m));
        }
        __syncthreads();
        for (int i = tid; i < 4096; i += NTHR)
            if (sh[i]) atomicAdd(&g_hist1[i], sh[i]);
        __syncthreads();
        for (int i = tid; i < 4096; i += NTHR) sh[i] = 0u;   // pre-zero for P2
    }
    gbar(1, true);

    // ------- P2: find1 (all blocks); refined histogram from REGISTERS -------
    u32 b1, above1;
    {
        u32* sh2 = (u32*)smraw;            // already zeroed pre-barrier
        find_bucket(g_hist1, PRE_TOPN, ws, sres, b1, above1);
        if (bid == 0 && tid < 32)
            g_invalid[tid] = (tid == 31) ? 0xFFFFFFFFFFFF0000ULL : 0ULL;
#pragma unroll
        for (int j = 0; j < 12; j++) {
            if (j >= nf) break;
            u32 k = fkey(f[j]);
            if ((k >> 20) == b1) atomicAdd(&sh2[(k >> 8) & 0xFFFu], 1u);
        }
        __syncthreads();
        for (int i = tid; i < 4096; i += NTHR)
            if (sh2[i]) atomicAdd(&g_hist2[i], sh2[i]);
    }
    gbar(2, true);

    // ------- P3: find2 (all blocks); gather candidates from REGISTERS -------
    {
        u32 b2, dummy;
        find_bucket(g_hist2, PRE_TOPN - above1, ws, sres, b2, dummy);
        u32 thr24 = (b1 << 12) | b2;
#pragma unroll
        for (int j = 0; j < 12; j++) {
            if (j >= nf) break;
            u32 k = fkey(f[j]);
            bool pred = ((k >> 8) >= thr24);
            int m = (i0 + (j >> 2) * GSTRIDE) * 4 + (j & 3);
            int a = m >> 19;
            int shw = m & (SHW - 1);
            u32 r = (u32)(shw * A_NUM + a);
            u64 item = ((u64)k << 32) | (0xFFFFFFFFu - r);
            wappend(pred, item, &g_ccount, g_cand, CAND_CAP);
        }
        for (int i = i0; i < 4096; i += GSTRIDE) g_hist1[i] = 0u;   // replay reset
    }
    gbar(3, true);

    // ------ P4: rank (warp per candidate, full smem staging) + decode ------
    {
        int cc = g_ccount; if (cc > CAND_CAP) cc = CAND_CAP;
        u64* st = (u64*)smraw;                       // <=4096 u64 = 32KB
        for (int j = tid; j < cc; j += NTHR) st[j] = g_cand[j];
        __syncthreads();
        int w = tid >> 5;
        int c = bid * 32 + w;                        // capacity 4736 >= cc
        if (c < cc) {
            u64 myk = st[c];
            u32 partial = 0;
            for (int j = lane; j < cc; j += 32) partial += (st[j] > myk);
#pragma unroll
            for (int off = 16; off > 0; off >>= 1)
                partial += __shfl_xor_sync(0xFFFFFFFFu, partial, off);
            if (lane == 0) {
                int rank = (int)partial;
                if (rank < PRE_TOPN) decode_box(myk, rank, deltas, imi, anchors);
            }
        }
        for (int i = i0; i < 4096; i += GSTRIDE) g_hist2[i] = 0u;   // replay reset
    }
    gbar(4, true);

    // ---- P5: IoU masks ONLY for rows < 512 (tiles rb<8); full 32 cols ----
    {
        if (bid == 0 && tid == 0) g_ccount = 0;      // reset for next replay
        float4* cbbv = (float4*)smraw + (tid >> 6) * 128;   // [64][2] float4 per group
        int grp = tid >> 6, lt = tid & 63;
        int t = bid * 16 + grp;                      // tile slot; need t<256
        int rb = t >> 5, cbi = t & 31;
        bool inr  = (t < 256);
        bool act  = inr && (cbi >= rb);
        bool zero = inr && (cbi < rb);
        if (act) {
            int j = cbi * 64 + lt;
            if (j < PRE_TOPN) {
                cbbv[lt * 2 + 0] = g_bx4[j * 2 + 0];
                cbbv[lt * 2 + 1] = g_bx4[j * 2 + 1];
            }
        }
        __syncthreads();
        if (zero) g_mask[(rb * 64 + lt) * MASK_COLS + cbi] = 0ULL;
        if (act) {
            int i = rb * 64 + lt;                    // < 512 < PRE_TOPN
            float4 lo = g_bx4[i * 2 + 0];
            float4 hi = g_bx4[i * 2 + 1];
            g_mask[i * MASK_COLS + cbi] =
                mask_word(i, cbi, lo.x, lo.y, lo.z, lo.w, hi.x, hi.y, hi.z, cbbv);
        }
    }
    gbar(5, false);   // arrive-only for non-zero blocks

    if (bid != 0) return;

    // ------------- P6: batch NMS over chunks (block 0) + output -------------
    {
        u64* buf    = (u64*)smraw;                 // 2 x 2048 u64 = 32KB
        int* keep_s = (int*)(smraw + 32768);       // 300 ints
        int* s_nk   = (int*)(smraw + 32768 + 1200);
        int* s_flag = (int*)(smraw + 32768 + 1204);
        if (tid == 0) { *s_flag = 0; *s_nk = 0; }
        u64 remv = 0ULL;
        if (tid < 32) remv = g_invalid[tid];
        for (int k = tid; k < 64 * MASK_COLS; k += NTHR) buf[k] = g_mask[k];
        __syncthreads();

        int nk = 0;
        for (int c = 0; c < MASK_COLS; c++) {
            if (c == CHUNKS_FAST) {
                // FALLBACK (nk < 300 after 512 rows): compute remaining tiles
                // (rows >= 512) reading boxes straight from L2, then restage.
                int grp = tid >> 6, lt = tid & 63;
                for (int tb = 256; tb < 1024; tb += 16) {
                    int t = tb + grp;
                    int rb = t >> 5, cbi = t & 31;
                    int i = rb * 64 + lt;
                    if (i < PRE_TOPN) {
                        if (cbi < rb) {
                            g_mask[i * MASK_COLS + cbi] = 0ULL;
                        } else {
                            float4 lo = g_bx4[i * 2 + 0];
                            float4 hi = g_bx4[i * 2 + 1];
                            u64 word = 0ULL;
                            int jn = min(64, PRE_TOPN - cbi * 64);
                            for (int jj = 0; jj < jn; jj++) {
                                int jg = cbi * 64 + jj;
                                if (jg <= i) continue;
                                float4 cl = g_bx4[jg * 2 + 0];
                                float4 ch = g_bx4[jg * 2 + 1];
                                float iw  = fminf(lo.w, cl.w) - fmaxf(lo.x, cl.x) + 1.0f;
                                float ih  = fminf(hi.x, ch.x) - fmaxf(lo.y, cl.y) + 1.0f;
                                float idd = fminf(hi.y, ch.y) - fmaxf(lo.z, cl.z) + 1.0f;
                                iw = fmaxf(iw, 0.0f); ih = fmaxf(ih, 0.0f); idd = fmaxf(idd, 0.0f);
                                float inter = iw * ih * idd;
                                float iou = inter / (hi.z + ch.z - inter);
                                if (iou > NMS_T) word |= (1ULL << jj);
                            }
                            g_mask[i * MASK_COLS + cbi] = word;
                        }
                    }
                }
                __syncthreads();
                // stage chunk 8
                for (int k = tid; k < 64 * MASK_COLS; k += NTHR)
                    buf[(CHUNKS_FAST & 1) * 2048 + k] =
                        g_mask[CHUNKS_FAST * 64 * MASK_COLS + k];
                __syncthreads();
            }
            // prefetch next chunk (skip prefetching into the fallback boundary)
            if (tid >= 32 && c + 1 < MASK_COLS && c + 1 != CHUNKS_FAST) {
                int r0n = (c + 1) * 64;
                int rnn = min(64, PRE_TOPN - r0n);
                u64* dst = buf + ((c + 1) & 1) * 2048;
                for (int k = tid - 32; k < rnn * MASK_COLS; k += (NTHR - 32))
                    dst[k] = g_mask[r0n * MASK_COLS + k];
            }
            if (tid < 32) {
                const u64* sb = buf + (c & 1) * 2048;
                u64 mcA = sb[lane * MASK_COLS + c];
                u64 mcB = sb[(lane + 32) * MASK_COLS + c];
                u64 cur = __shfl_sync(0xFFFFFFFFu, remv, c);
                u64 K = ~cur;                      // speculative keep set
                while (true) {
                    u64 contrib = 0ULL;
                    if ((K >> lane) & 1ULL) contrib = mcA;
                    if ((K >> (lane + 32)) & 1ULL) contrib |= mcB;
                    u32 ulo = __reduce_or_sync(0xFFFFFFFFu, (u32)contrib);
                    u32 uhi = __reduce_or_sync(0xFFFFFFFFu, (u32)(contrib >> 32));
                    u64 V = K & (((u64)uhi << 32) | ulo);
                    if (!V) break;
                    K &= ~(V & (~V + 1ULL));       // drop first genuine suppressee
                }
                int cnt = __popcll(K);
                int take = min(cnt, POST_TOPN - nk);
                u64 C = K;
                for (int d = cnt - take; d > 0; d--)
                    C &= ~(0x8000000000000000ULL >> __clzll(C));
                if ((C >> lane) & 1ULL) {
                    int pos = nk + (int)__popcll(C & ((1ULL << lane) - 1ULL));
                    keep_s[pos] = c * 64 + lane;
                }
                if ((C >> (lane + 32)) & 1ULL) {
                    int pos = nk + (int)__popcll(C & ((1ULL << (lane + 32)) - 1ULL));
                    keep_s[pos] = c * 64 + lane + 32;
                }
                nk += take;
                u64 CC = C;
                while (CC) {
                    int b = __ffsll((long long)CC) - 1;
                    CC &= CC - 1ULL;
                    remv |= sb[b * MASK_COLS + lane];
                }
                if (lane == 0 && (nk >= POST_TOPN || c == MASK_COLS - 1)) {
                    *s_nk = nk; *s_flag = 1;
                }
            }
            __syncthreads();
            if (*s_flag) break;
        }

        int nkf = *s_nk;
        float* rois = out;
        float* sc   = out + POST_TOPN * 7;
        float* ki   = out + POST_TOPN * 7 + POST_TOPN;
        float* sv   = out + POST_TOPN * 7 + 2 * POST_TOPN;
        for (int p = tid; p < POST_TOPN; p += NTHR) {
            if (p < nkf) {
                int i = keep_s[p];
                float4 lo = g_bx4[i * 2 + 0];
                float4 hi = g_bx4[i * 2 + 1];
                rois[p * 7 + 0] = 0.0f;
                rois[p * 7 + 1] = lo.x;
                rois[p * 7 + 2] = lo.y;
                rois[p * 7 + 3] = lo.z;
                rois[p * 7 + 4] = lo.w;
                rois[p * 7 + 5] = hi.x;
                rois[p * 7 + 6] = hi.y;
                sc[p] = g_score[i];
                ki[p] = (float)g_order[i];
                sv[p] = 1.0f;
            } else {
#pragma unroll
                for (int q = 0; q < 7; q++) rois[p * 7 + q] = 0.0f;
                sc[p] = 0.0f;
                ki[p] = -1.0f;
                sv[p] = 0.0f;
            }
        }
        // reset barrier state for next graph replay (all arrivals observed)
        __syncthreads();
        if (tid < NBLK) g_arrive[tid] = 0u;
        if (tid == 0) g_release = 0u;
    }
}

extern "C" void kernel_launch(void* const* d_in, const int* in_sizes, int n_in,
                              void* d_out, int out_size) {
    const float4* scores = (const float4*)d_in[0];
    const float*  deltas = (const float*)d_in[1];
    const float*  im_info = (const float*)d_in[2];
    const float*  anchors = (const float*)d_in[3];
    float* out = (float*)d_out;
    k_all<<<NBLK, NTHR>>>(scores, deltas, im_info, anchors, out);
    (void)in_sizes; (void)n_in; (void)out_size;
}